// round 15
// baseline (speedup 1.0000x reference)
#include <cuda_runtime.h>
#include <cuda_fp16.h>
#include <cstdint>
#include <math.h>

// MoE top-2/16, fp32 in/out. R14 = R12 pipeline, but ffn mainloop re-tiled:
// CTA 128x128, FOUR warps (2m x 2n), warp tile 64x64 -> smem fragment
// duplication drops from (A2x + B4x) to (A2x + B2x): 128KB -> 96KB per chunk,
// lifting the smem-crossbar ceiling that bound the tensor pipe at 47%.

#define D_MODEL 1024
#define N_EXP   16
#define D_FF    4096
#define N_TOK   4096
#define MAXPE   4096
#define NSLOT   (2 * N_TOK)

__device__ int    g_count[N_EXP];
__device__ int    g_offset[N_EXP + 1];
__device__ int    g_tok[N_EXP * MAXPE];
__device__ float  g_wt[N_EXP * MAXPE];
__device__ int    g_exp[N_TOK * 2];
__device__ int    g_pos[N_TOK * 2];
__device__ __half g_W1t[(size_t)N_EXP * D_FF * D_MODEL];   // [e][n][k]
__device__ __half g_W2t[(size_t)N_EXP * D_MODEL * D_FF];   // [e][n][k]
__device__ __half g_A[(size_t)NSLOT * D_MODEL];
__device__ __half g_Hf[(size_t)NSLOT * D_FF];
__device__ float  g_O[(size_t)NSLOT * D_MODEL];

// ---------------------------------------------------------------------------
__device__ __forceinline__ uint32_t smem_to_u32(const void* p) {
    uint32_t a;
    asm("{ .reg .u64 t; cvta.to.shared.u64 t, %1; cvt.u32.u64 %0, t; }" : "=r"(a) : "l"(p));
    return a;
}
__device__ __forceinline__ void cp16(uint32_t dst, const void* src) {
    asm volatile("cp.async.cg.shared.global [%0], [%1], 16;" :: "r"(dst), "l"(src));
}
#define CP_COMMIT() asm volatile("cp.async.commit_group;" ::: "memory")
#define CP_WAIT1()  asm volatile("cp.async.wait_group 1;" ::: "memory")

#define LDSM_X4(r, a)                                                            \
    asm volatile("ldmatrix.sync.aligned.m8n8.x4.shared.b16 {%0,%1,%2,%3}, [%4];" \
        : "=r"((r)[0]), "=r"((r)[1]), "=r"((r)[2]), "=r"((r)[3]) : "r"(a))

__device__ __forceinline__ void mma_f16(float* d, const uint32_t* a, const uint32_t* b) {
    asm volatile("mma.sync.aligned.m16n8k16.row.col.f32.f16.f16.f32 "
        "{%0,%1,%2,%3}, {%4,%5,%6,%7}, {%8,%9}, {%0,%1,%2,%3};"
        : "+f"(d[0]), "+f"(d[1]), "+f"(d[2]), "+f"(d[3])
        : "r"(a[0]), "r"(a[1]), "r"(a[2]), "r"(a[3]), "r"(b[0]), "r"(b[1]));
}

__device__ __forceinline__ uint32_t packf16(float a, float b) {
    uint32_t r;
    asm("cvt.rn.f16x2.f32 %0, %1, %2;" : "=r"(r) : "f"(b), "f"(a));
    return r;
}

// ---------------------------------------------------------------------------
// reset / gating / offsets / gatherx / convW (all validated, R12 structure)
// ---------------------------------------------------------------------------
__global__ void reset_kernel() {
    if (threadIdx.x < N_EXP) g_count[threadIdx.x] = 0;
}

__global__ void gating_kernel(const float* __restrict__ x, const float* __restrict__ Wg) {
    int warp = (blockIdx.x * blockDim.x + threadIdx.x) >> 5;
    int lane = threadIdx.x & 31;
    if (warp >= N_TOK) return;
    const float* xr = x + (size_t)warp * D_MODEL;
    float acc[N_EXP];
#pragma unroll
    for (int e = 0; e < N_EXP; e++) acc[e] = 0.0f;
    for (int d = lane; d < D_MODEL; d += 32) {
        float xv = xr[d];
        const float* wr = Wg + d * N_EXP;
#pragma unroll
        for (int e = 0; e < N_EXP; e++) acc[e] = fmaf(xv, wr[e], acc[e]);
    }
#pragma unroll
    for (int e = 0; e < N_EXP; e++) {
#pragma unroll
        for (int o = 16; o > 0; o >>= 1) acc[e] += __shfl_xor_sync(0xffffffffu, acc[e], o);
    }
    if (lane == 0) {
        int i1 = 0; float v1 = acc[0];
#pragma unroll
        for (int e = 1; e < N_EXP; e++) if (acc[e] > v1) { v1 = acc[e]; i1 = e; }
        int i2 = -1; float v2 = -INFINITY;
#pragma unroll
        for (int e = 0; e < N_EXP; e++) if (e != i1 && acc[e] > v2) { v2 = acc[e]; i2 = e; }
        float e2 = expf(v2 - v1);
        float inv = 1.0f / (1.0f + e2);
        int s1 = atomicAdd(&g_count[i1], 1);
        g_tok[i1 * MAXPE + s1] = warp;  g_wt[i1 * MAXPE + s1] = inv;
        int s2 = atomicAdd(&g_count[i2], 1);
        g_tok[i2 * MAXPE + s2] = warp;  g_wt[i2 * MAXPE + s2] = e2 * inv;
        g_exp[warp * 2 + 0] = i1;  g_pos[warp * 2 + 0] = s1;
        g_exp[warp * 2 + 1] = i2;  g_pos[warp * 2 + 1] = s2;
    }
}

__global__ void offsets_kernel() {
    int s = 0;
    for (int e = 0; e < N_EXP; e++) { g_offset[e] = s; s += g_count[e]; }
    g_offset[N_EXP] = s;
}

__global__ void gatherx_kernel(const float* __restrict__ x) {
    int s = blockIdx.x;
    if (s >= g_offset[N_EXP]) return;
    int e = 0;
#pragma unroll
    for (int i = 0; i < N_EXP - 1; i++) if (s >= g_offset[i + 1]) e = i + 1;
    int tok = g_tok[e * MAXPE + (s - g_offset[e])];
    const float* xr = x + (size_t)tok * D_MODEL;
    int c = threadIdx.x * 8;
    float4 a = *reinterpret_cast<const float4*>(xr + c);
    float4 b = *reinterpret_cast<const float4*>(xr + c + 4);
    uint4 o;
    o.x = packf16(a.x, a.y);
    o.y = packf16(a.z, a.w);
    o.z = packf16(b.x, b.y);
    o.w = packf16(b.z, b.w);
    *reinterpret_cast<uint4*>(g_A + (size_t)s * D_MODEL + c) = o;
}

template <int WHICH>
__global__ void convW_kernel(const float* __restrict__ src) {
    constexpr int K = (WHICH == 1) ? D_MODEL : D_FF;
    constexpr int N = (WHICH == 1) ? D_FF : D_MODEL;
    __half* dstBase = (WHICH == 1) ? g_W1t : g_W2t;
    __shared__ float t[64][65];
    int e  = blockIdx.z;
    int k0 = blockIdx.y * 64;
    int n0 = blockIdx.x * 64;
    const float* S = src + (size_t)e * K * N;
    int tid = threadIdx.x;
    int rk = tid >> 4;
    int cn = (tid & 15) * 4;
#pragma unroll
    for (int p = 0; p < 4; p++) {
        float4 v = *reinterpret_cast<const float4*>(S + (size_t)(k0 + p * 16 + rk) * N + n0 + cn);
        t[p * 16 + rk][cn + 0] = v.x;
        t[p * 16 + rk][cn + 1] = v.y;
        t[p * 16 + rk][cn + 2] = v.z;
        t[p * 16 + rk][cn + 3] = v.w;
    }
    __syncthreads();
    int n  = tid >> 2;
    int kq = (tid & 3) * 16;
    uint32_t w[8];
#pragma unroll
    for (int q = 0; q < 8; q++)
        w[q] = packf16(t[kq + 2 * q][n], t[kq + 2 * q + 1][n]);
    __half* D = dstBase + (size_t)e * N * K + (size_t)(n0 + n) * K + k0 + kq;
    *reinterpret_cast<uint4*>(D)     = make_uint4(w[0], w[1], w[2], w[3]);
    *reinterpret_cast<uint4*>(D + 8) = make_uint4(w[4], w[5], w[6], w[7]);
}

// ---------------------------------------------------------------------------
// Grouped GEMM, fp16. CTA 128x128, 4 warps (2m x 2n), warp tile 64x64.
// Stage: A 16K | B 16K = 32K; 3 stages; cp.async depth 2; 2 CTAs/SM.
// Swizzle: 16B chunk c of 128B row r at (c ^ (r&7)).
// ---------------------------------------------------------------------------
#define A_OFF 0
#define B_OFF 16384
#define STG   32768
#define SMEM_BYTES (3 * STG)

template <int PHASE>
__global__ __launch_bounds__(128, 2)
void ffn_kernel(const float* __restrict__ bias)
{
    constexpr int KTOT = (PHASE == 1) ? D_MODEL : D_FF;
    constexpr int NTOT = (PHASE == 1) ? D_FF : D_MODEL;
    constexpr int L    = KTOT / 64;

    const int e   = blockIdx.z;
    const int cnt = g_count[e];
    const int m0  = blockIdx.x * 128;
    if (m0 >= cnt) return;
    const int n0    = blockIdx.y * 128;
    const int e_off = g_offset[e];

    const __half* Aa = (PHASE == 1) ? g_A : g_Hf;
    const __half* Be = ((PHASE == 1) ? g_W1t : g_W2t) + (size_t)e * NTOT * KTOT;

    extern __shared__ char smem[];
    const uint32_t smem_u = smem_to_u32(smem);
    const int tid  = threadIdx.x;
    const int lane = tid & 31;
    const int wid  = tid >> 5;        // 0..3
    const int wm   = wid >> 1;        // 0..1 -> rows wm*64
    const int wn   = wid & 1;         // 0..1 -> cols wn*64

    // cp.async: 8 (row, c) pairs per thread per matrix; row = tid>>3 + 16*i,
    // c = tid&7 (constant). (row&7) is i-invariant -> dOff strides by 2048.
    const int  cpc   = tid & 7;
    const int  row0  = tid >> 3;                     // 0..15
    const uint32_t dOff0 = row0 * 128 + ((cpc ^ (row0 & 7)) << 4);
    const __half* sA[8];
#pragma unroll
    for (int i = 0; i < 8; i++) {
        int row = row0 + 16 * i;
        int slot = m0 + row; if (slot >= cnt) slot = cnt - 1;
        sA[i] = Aa + (size_t)(e_off + slot) * KTOT + cpc * 8;
    }
    const __half* sB0 = Be + (size_t)(n0 + row0) * KTOT + cpc * 8;

    // ldmatrix lane addressing (same formulas as validated R5..R12; mb now 0..3)
    const int a_row0 = wm * 64 + (lane & 7) + (lane & 8);
    const int a_kt   = (lane >> 4) & 1;
    const int b_row0 = wn * 64 + (lane & 7) + ((lane & 16) ? 8 : 0);
    const int b_kt   = (lane >> 3) & 1;

    float acc[4][8][4];
#pragma unroll
    for (int mb = 0; mb < 4; mb++)
#pragma unroll
        for (int nb = 0; nb < 8; nb++)
#pragma unroll
            for (int q = 0; q < 4; q++) acc[mb][nb][q] = 0.0f;

    // prologue: prefetch stages 0, 1
#pragma unroll
    for (int p = 0; p < 2; p++) {
        uint32_t st = smem_u + p * STG;
        int k0 = p * 64;
#pragma unroll
        for (int i = 0; i < 8; i++) {
            cp16(st + A_OFF + dOff0 + i * 2048, sA[i] + k0);
            cp16(st + B_OFF + dOff0 + i * 2048, sB0 + (size_t)(16 * i) * KTOT + k0);
        }
        CP_COMMIT();
    }

    int slot_c = 0;
    for (int c = 0; c < L; c++) {
        CP_WAIT1();
        __syncthreads();
        if (c + 2 < L) {
            int sl = slot_c + 2; if (sl >= 3) sl -= 3;
            uint32_t st = smem_u + sl * STG;
            int k0 = (c + 2) * 64;
#pragma unroll
            for (int i = 0; i < 8; i++) {
                cp16(st + A_OFF + dOff0 + i * 2048, sA[i] + k0);
                cp16(st + B_OFF + dOff0 + i * 2048, sB0 + (size_t)(16 * i) * KTOT + k0);
            }
        }
        CP_COMMIT();

        const uint32_t st = smem_u + slot_c * STG;
#pragma unroll
        for (int ks = 0; ks < 4; ks++) {
            uint32_t aa[4][4], bb[4][4];
#pragma unroll
            for (int mb = 0; mb < 4; mb++) {
                int row = a_row0 + mb * 16;
                uint32_t off = row * 128 + (((2 * ks + a_kt) ^ (row & 7)) << 4);
                LDSM_X4(aa[mb], st + A_OFF + off);
            }
#pragma unroll
            for (int np = 0; np < 4; np++) {
                int row = b_row0 + np * 16;
                uint32_t off = row * 128 + (((2 * ks + b_kt) ^ (row & 7)) << 4);
                LDSM_X4(bb[np], st + B_OFF + off);
            }
#pragma unroll
            for (int mb = 0; mb < 4; mb++)
#pragma unroll
                for (int nb = 0; nb < 8; nb++)
                    mma_f16(acc[mb][nb], aa[mb], &bb[nb >> 1][(nb & 1) * 2]);
        }
        if (++slot_c == 3) slot_c = 0;
    }

    // epilogue: plain stores
    const int gp = lane >> 2;
    const int qq = lane & 3;
#pragma unroll
    for (int mb = 0; mb < 4; mb++) {
#pragma unroll
        for (int h = 0; h < 2; h++) {
            int mloc = wm * 64 + mb * 16 + gp + h * 8;
            int slot = m0 + mloc;
            if (slot >= cnt) continue;
            if (PHASE == 1) {
                size_t hrow = (size_t)(e_off + slot) * D_FF;
#pragma unroll
                for (int nb = 0; nb < 8; nb++) {
                    int cidx = n0 + wn * 64 + nb * 8 + qq * 2;
                    float v0 = acc[mb][nb][h * 2 + 0] + __ldg(bias + e * NTOT + cidx + 0);
                    float v1 = acc[mb][nb][h * 2 + 1] + __ldg(bias + e * NTOT + cidx + 1);
                    float s0 = v0 / (1.0f + __expf(-v0));
                    float s1 = v1 / (1.0f + __expf(-v1));
                    *reinterpret_cast<uint32_t*>(g_Hf + hrow + cidx) = packf16(s0, s1);
                }
            } else {
                float* orow = g_O + (size_t)(e_off + slot) * D_MODEL;
#pragma unroll
                for (int nb = 0; nb < 8; nb++) {
                    int cidx = n0 + wn * 64 + nb * 8 + qq * 2;
                    float v0 = acc[mb][nb][h * 2 + 0] + __ldg(bias + e * NTOT + cidx + 0);
                    float v1 = acc[mb][nb][h * 2 + 1] + __ldg(bias + e * NTOT + cidx + 1);
                    float2 o; o.x = v0; o.y = v1;
                    *reinterpret_cast<float2*>(orow + cidx) = o;
                }
            }
        }
    }
}

// ---------------------------------------------------------------------------
__global__ void combine_kernel(float* __restrict__ out) {
    int tok = blockIdx.x;
    int e1  = g_exp[tok * 2 + 0], e2 = g_exp[tok * 2 + 1];
    int p1  = g_pos[tok * 2 + 0], p2 = g_pos[tok * 2 + 1];
    float w1 = g_wt[e1 * MAXPE + p1];
    float w2 = g_wt[e2 * MAXPE + p2];
    const float* r1 = g_O + (size_t)(g_offset[e1] + p1) * D_MODEL;
    const float* r2 = g_O + (size_t)(g_offset[e2] + p2) * D_MODEL;
    int c = threadIdx.x * 4;
    float4 a = *reinterpret_cast<const float4*>(r1 + c);
    float4 b = *reinterpret_cast<const float4*>(r2 + c);
    float4 o;
    o.x = w1 * a.x + w2 * b.x;
    o.y = w1 * a.y + w2 * b.y;
    o.z = w1 * a.z + w2 * b.z;
    o.w = w1 * a.w + w2 * b.w;
    *reinterpret_cast<float4*>(out + (size_t)tok * D_MODEL + c) = o;
}

// ---------------------------------------------------------------------------
extern "C" void kernel_launch(void* const* d_in, const int* in_sizes, int n_in,
                              void* d_out, int out_size) {
    const float* x  = (const float*)d_in[0];
    const float* W1 = (const float*)d_in[1];
    const float* b1 = (const float*)d_in[2];
    const float* W2 = (const float*)d_in[3];
    const float* b2 = (const float*)d_in[4];
    const float* Wg = (const float*)d_in[5];
    float* out = (float*)d_out;

    cudaFuncSetAttribute(ffn_kernel<1>, cudaFuncAttributeMaxDynamicSharedMemorySize, SMEM_BYTES);
    cudaFuncSetAttribute(ffn_kernel<2>, cudaFuncAttributeMaxDynamicSharedMemorySize, SMEM_BYTES);

    reset_kernel<<<1, 32>>>();
    gating_kernel<<<N_TOK / 8, 256>>>(x, Wg);
    offsets_kernel<<<1, 1>>>();
    gatherx_kernel<<<NSLOT, 128>>>(x);
    convW_kernel<1><<<dim3(D_FF / 64, D_MODEL / 64, N_EXP), 256>>>(W1);
    convW_kernel<2><<<dim3(D_MODEL / 64, D_FF / 64, N_EXP), 256>>>(W2);
    ffn_kernel<1><<<dim3(MAXPE / 128, D_FF / 128, N_EXP), 128, SMEM_BYTES>>>(b1);
    ffn_kernel<2><<<dim3(MAXPE / 128, D_MODEL / 128, N_EXP), 128, SMEM_BYTES>>>(b2);
    combine_kernel<<<N_TOK, 256>>>(out);
}

// round 16
// speedup vs baseline: 1.0451x; 1.0451x over previous
#include <cuda_runtime.h>
#include <cuda_fp16.h>
#include <cstdint>
#include <math.h>

// MoE top-2/16, fp32 in/out. R16 = R12 structure (8 warps, 4m x 2n, 3-stage
// cp.async ring, 2 CTAs/SM) with:
//  (a) register diet: cp.async addresses recomputed from bases (no pointer
//      arrays) so the body fits the 128-reg cap of __launch_bounds__(256,2)
//      without spills;
//  (b) ffn2 split-K=2 (partials in g_O/g_O2, bias+sum in combine) to fix the
//      1.7-wave tail of ffn2.

#define D_MODEL 1024
#define N_EXP   16
#define D_FF    4096
#define N_TOK   4096
#define MAXPE   4096
#define NSLOT   (2 * N_TOK)

__device__ int    g_count[N_EXP];
__device__ int    g_offset[N_EXP + 1];
__device__ int    g_tok[N_EXP * MAXPE];
__device__ float  g_wt[N_EXP * MAXPE];
__device__ int    g_exp[N_TOK * 2];
__device__ int    g_pos[N_TOK * 2];
__device__ __half g_W1t[(size_t)N_EXP * D_FF * D_MODEL];   // [e][n][k]
__device__ __half g_W2t[(size_t)N_EXP * D_MODEL * D_FF];   // [e][n][k]
__device__ __half g_A[(size_t)NSLOT * D_MODEL];
__device__ __half g_Hf[(size_t)NSLOT * D_FF];
__device__ float  g_O [(size_t)NSLOT * D_MODEL];           // K-half 0 partial
__device__ float  g_O2[(size_t)NSLOT * D_MODEL];           // K-half 1 partial

// ---------------------------------------------------------------------------
__device__ __forceinline__ uint32_t smem_to_u32(const void* p) {
    uint32_t a;
    asm("{ .reg .u64 t; cvta.to.shared.u64 t, %1; cvt.u32.u64 %0, t; }" : "=r"(a) : "l"(p));
    return a;
}
__device__ __forceinline__ void cp16(uint32_t dst, const void* src) {
    asm volatile("cp.async.cg.shared.global [%0], [%1], 16;" :: "r"(dst), "l"(src));
}
#define CP_COMMIT() asm volatile("cp.async.commit_group;" ::: "memory")
#define CP_WAIT1()  asm volatile("cp.async.wait_group 1;" ::: "memory")

#define LDSM_X4(r, a)                                                            \
    asm volatile("ldmatrix.sync.aligned.m8n8.x4.shared.b16 {%0,%1,%2,%3}, [%4];" \
        : "=r"((r)[0]), "=r"((r)[1]), "=r"((r)[2]), "=r"((r)[3]) : "r"(a))

__device__ __forceinline__ void mma_f16(float* d, const uint32_t* a, const uint32_t* b) {
    asm volatile("mma.sync.aligned.m16n8k16.row.col.f32.f16.f16.f32 "
        "{%0,%1,%2,%3}, {%4,%5,%6,%7}, {%8,%9}, {%0,%1,%2,%3};"
        : "+f"(d[0]), "+f"(d[1]), "+f"(d[2]), "+f"(d[3])
        : "r"(a[0]), "r"(a[1]), "r"(a[2]), "r"(a[3]), "r"(b[0]), "r"(b[1]));
}

__device__ __forceinline__ uint32_t packf16(float a, float b) {
    uint32_t r;
    asm("cvt.rn.f16x2.f32 %0, %1, %2;" : "=r"(r) : "f"(b), "f"(a));
    return r;
}

// ---------------------------------------------------------------------------
// reset / gating / offsets / gatherx / convW (validated, unchanged)
// ---------------------------------------------------------------------------
__global__ void reset_kernel() {
    if (threadIdx.x < N_EXP) g_count[threadIdx.x] = 0;
}

__global__ void gating_kernel(const float* __restrict__ x, const float* __restrict__ Wg) {
    int warp = (blockIdx.x * blockDim.x + threadIdx.x) >> 5;
    int lane = threadIdx.x & 31;
    if (warp >= N_TOK) return;
    const float* xr = x + (size_t)warp * D_MODEL;
    float acc[N_EXP];
#pragma unroll
    for (int e = 0; e < N_EXP; e++) acc[e] = 0.0f;
    for (int d = lane; d < D_MODEL; d += 32) {
        float xv = xr[d];
        const float* wr = Wg + d * N_EXP;
#pragma unroll
        for (int e = 0; e < N_EXP; e++) acc[e] = fmaf(xv, wr[e], acc[e]);
    }
#pragma unroll
    for (int e = 0; e < N_EXP; e++) {
#pragma unroll
        for (int o = 16; o > 0; o >>= 1) acc[e] += __shfl_xor_sync(0xffffffffu, acc[e], o);
    }
    if (lane == 0) {
        int i1 = 0; float v1 = acc[0];
#pragma unroll
        for (int e = 1; e < N_EXP; e++) if (acc[e] > v1) { v1 = acc[e]; i1 = e; }
        int i2 = -1; float v2 = -INFINITY;
#pragma unroll
        for (int e = 0; e < N_EXP; e++) if (e != i1 && acc[e] > v2) { v2 = acc[e]; i2 = e; }
        float e2 = expf(v2 - v1);
        float inv = 1.0f / (1.0f + e2);
        int s1 = atomicAdd(&g_count[i1], 1);
        g_tok[i1 * MAXPE + s1] = warp;  g_wt[i1 * MAXPE + s1] = inv;
        int s2 = atomicAdd(&g_count[i2], 1);
        g_tok[i2 * MAXPE + s2] = warp;  g_wt[i2 * MAXPE + s2] = e2 * inv;
        g_exp[warp * 2 + 0] = i1;  g_pos[warp * 2 + 0] = s1;
        g_exp[warp * 2 + 1] = i2;  g_pos[warp * 2 + 1] = s2;
    }
}

__global__ void offsets_kernel() {
    int s = 0;
    for (int e = 0; e < N_EXP; e++) { g_offset[e] = s; s += g_count[e]; }
    g_offset[N_EXP] = s;
}

__global__ void gatherx_kernel(const float* __restrict__ x) {
    int s = blockIdx.x;
    if (s >= g_offset[N_EXP]) return;
    int e = 0;
#pragma unroll
    for (int i = 0; i < N_EXP - 1; i++) if (s >= g_offset[i + 1]) e = i + 1;
    int tok = g_tok[e * MAXPE + (s - g_offset[e])];
    const float* xr = x + (size_t)tok * D_MODEL;
    int c = threadIdx.x * 8;
    float4 a = *reinterpret_cast<const float4*>(xr + c);
    float4 b = *reinterpret_cast<const float4*>(xr + c + 4);
    uint4 o;
    o.x = packf16(a.x, a.y);
    o.y = packf16(a.z, a.w);
    o.z = packf16(b.x, b.y);
    o.w = packf16(b.z, b.w);
    *reinterpret_cast<uint4*>(g_A + (size_t)s * D_MODEL + c) = o;
}

template <int WHICH>
__global__ void convW_kernel(const float* __restrict__ src) {
    constexpr int K = (WHICH == 1) ? D_MODEL : D_FF;
    constexpr int N = (WHICH == 1) ? D_FF : D_MODEL;
    __half* dstBase = (WHICH == 1) ? g_W1t : g_W2t;
    __shared__ float t[64][65];
    int e  = blockIdx.z;
    int k0 = blockIdx.y * 64;
    int n0 = blockIdx.x * 64;
    const float* S = src + (size_t)e * K * N;
    int tid = threadIdx.x;
    int rk = tid >> 4;
    int cn = (tid & 15) * 4;
#pragma unroll
    for (int p = 0; p < 4; p++) {
        float4 v = *reinterpret_cast<const float4*>(S + (size_t)(k0 + p * 16 + rk) * N + n0 + cn);
        t[p * 16 + rk][cn + 0] = v.x;
        t[p * 16 + rk][cn + 1] = v.y;
        t[p * 16 + rk][cn + 2] = v.z;
        t[p * 16 + rk][cn + 3] = v.w;
    }
    __syncthreads();
    int n  = tid >> 2;
    int kq = (tid & 3) * 16;
    uint32_t w[8];
#pragma unroll
    for (int q = 0; q < 8; q++)
        w[q] = packf16(t[kq + 2 * q][n], t[kq + 2 * q + 1][n]);
    __half* D = dstBase + (size_t)e * N * K + (size_t)(n0 + n) * K + k0 + kq;
    *reinterpret_cast<uint4*>(D)     = make_uint4(w[0], w[1], w[2], w[3]);
    *reinterpret_cast<uint4*>(D + 8) = make_uint4(w[4], w[5], w[6], w[7]);
}

// ---------------------------------------------------------------------------
// Grouped GEMM, fp16. CTA 128x128, 8 warps (4m x 2n), warp tile 32x64.
// Stage: A 16K | B 16K = 32K; 3 stages; cp.async depth 2; 2 CTAs/SM.
// Addresses recomputed per issue (no cached pointer arrays -> fits 128 regs).
// PHASE 2 is split-K: blockIdx.y in [0,16), kh = y>>3 selects K half; partial
// sums (no bias) stored to g_O / g_O2.
// ---------------------------------------------------------------------------
#define A_OFF 0
#define B_OFF 16384
#define STG   32768
#define SMEM_BYTES (3 * STG)

template <int PHASE>
__global__ __launch_bounds__(256, 2)
void ffn_kernel(const float* __restrict__ bias)
{
    constexpr int KTOT = (PHASE == 1) ? D_MODEL : D_FF;
    constexpr int NTOT = (PHASE == 1) ? D_FF : D_MODEL;
    constexpr int L    = (PHASE == 1) ? (KTOT / 64) : (KTOT / 128);  // per-CTA chunks

    const int e   = blockIdx.z;
    const int cnt = g_count[e];
    const int m0  = blockIdx.x * 128;
    if (m0 >= cnt) return;
    const int kh    = (PHASE == 1) ? 0 : (blockIdx.y >> 3);
    const int n0    = ((PHASE == 1) ? blockIdx.y : (blockIdx.y & 7)) * 128;
    const int kbase = kh * (KTOT / 2);
    const int e_off = g_offset[e];

    const __half* Aa = ((PHASE == 1) ? g_A : g_Hf) + kbase;
    const __half* Be = ((PHASE == 1) ? g_W1t : g_W2t) + (size_t)e * NTOT * KTOT + kbase;

    extern __shared__ char smem[];
    const uint32_t smem_u = smem_to_u32(smem);
    const int tid  = threadIdx.x;
    const int lane = tid & 31;
    const int wid  = tid >> 5;
    const int wm   = wid >> 1;
    const int wn   = wid & 1;

    // cp.async geometry: thread covers (row0 + 32i, cpc) for i in 0..3.
    // (row&7) is i-invariant -> dOff strides by 4096.
    const int cpc  = tid & 7;
    const int row0 = tid >> 3;                    // 0..31
    const uint32_t dOff0 = row0 * 128 + ((cpc ^ (row0 & 7)) << 4);
    const __half* Arow0 = Aa + cpc * 8;           // + slot*KTOT per issue
    const __half* Brow0 = Be + (size_t)(n0 + row0) * KTOT + cpc * 8;

    // ldmatrix lane addressing (validated R5..R12)
    const int a_row0 = wm * 32 + (lane & 7) + (lane & 8);
    const int a_kt   = (lane >> 4) & 1;
    const int b_row0 = wn * 64 + (lane & 7) + ((lane & 16) ? 8 : 0);
    const int b_kt   = (lane >> 3) & 1;

    float acc[2][8][4];
#pragma unroll
    for (int mb = 0; mb < 2; mb++)
#pragma unroll
        for (int nb = 0; nb < 8; nb++)
#pragma unroll
            for (int q = 0; q < 4; q++) acc[mb][nb][q] = 0.0f;

    // issue one stage of cp.async (addresses recomputed, no cached arrays)
    auto issue_stage = [&](int st_slot, int k0) {
        uint32_t st = smem_u + st_slot * STG;
#pragma unroll
        for (int i = 0; i < 4; i++) {
            int row  = row0 + 32 * i;
            int slot = m0 + row; if (slot >= cnt) slot = cnt - 1;
            cp16(st + A_OFF + dOff0 + i * 4096,
                 Arow0 + (size_t)(e_off + slot) * KTOT + k0);
            cp16(st + B_OFF + dOff0 + i * 4096,
                 Brow0 + (size_t)(32 * i) * KTOT + k0);
        }
    };

#pragma unroll
    for (int p = 0; p < 2; p++) {
        issue_stage(p, p * 64);
        CP_COMMIT();
    }

    int slot_c = 0;
    for (int c = 0; c < L; c++) {
        CP_WAIT1();
        __syncthreads();
        if (c + 2 < L) {
            int sl = slot_c + 2; if (sl >= 3) sl -= 3;
            issue_stage(sl, (c + 2) * 64);
        }
        CP_COMMIT();

        const uint32_t st = smem_u + slot_c * STG;
#pragma unroll
        for (int ks = 0; ks < 4; ks++) {
            uint32_t aa[2][4], bb[4][4];
#pragma unroll
            for (int mb = 0; mb < 2; mb++) {
                int row = a_row0 + mb * 16;
                uint32_t off = row * 128 + (((2 * ks + a_kt) ^ (row & 7)) << 4);
                LDSM_X4(aa[mb], st + A_OFF + off);
            }
#pragma unroll
            for (int np = 0; np < 4; np++) {
                int row = b_row0 + np * 16;
                uint32_t off = row * 128 + (((2 * ks + b_kt) ^ (row & 7)) << 4);
                LDSM_X4(bb[np], st + B_OFF + off);
            }
#pragma unroll
            for (int mb = 0; mb < 2; mb++)
#pragma unroll
                for (int nb = 0; nb < 8; nb++)
                    mma_f16(acc[mb][nb], aa[mb], &bb[nb >> 1][(nb & 1) * 2]);
        }
        if (++slot_c == 3) slot_c = 0;
    }

    // epilogue
    const int gp = lane >> 2;
    const int qq = lane & 3;
#pragma unroll
    for (int mb = 0; mb < 2; mb++) {
#pragma unroll
        for (int h = 0; h < 2; h++) {
            int mloc = wm * 32 + mb * 16 + gp + h * 8;
            int slot = m0 + mloc;
            if (slot >= cnt) continue;
            if (PHASE == 1) {
                size_t hrow = (size_t)(e_off + slot) * D_FF;
#pragma unroll
                for (int nb = 0; nb < 8; nb++) {
                    int cidx = n0 + wn * 64 + nb * 8 + qq * 2;
                    float v0 = acc[mb][nb][h * 2 + 0] + __ldg(bias + e * NTOT + cidx + 0);
                    float v1 = acc[mb][nb][h * 2 + 1] + __ldg(bias + e * NTOT + cidx + 1);
                    float s0 = v0 / (1.0f + __expf(-v0));
                    float s1 = v1 / (1.0f + __expf(-v1));
                    *reinterpret_cast<uint32_t*>(g_Hf + hrow + cidx) = packf16(s0, s1);
                }
            } else {
                float* obase = ((kh == 0) ? g_O : g_O2) + (size_t)(e_off + slot) * D_MODEL;
#pragma unroll
                for (int nb = 0; nb < 8; nb++) {
                    int cidx = n0 + wn * 64 + nb * 8 + qq * 2;
                    float2 o;
                    o.x = acc[mb][nb][h * 2 + 0];
                    o.y = acc[mb][nb][h * 2 + 1];
                    *reinterpret_cast<float2*>(obase + cidx) = o;
                }
            }
        }
    }
}

// ---------------------------------------------------------------------------
// Combine: out[tok] = w1*(Oa[s1]+Ob[s1]+b2[e1]) + w2*(Oa[s2]+Ob[s2]+b2[e2]).
// ---------------------------------------------------------------------------
__global__ void combine_kernel(const float* __restrict__ b2, float* __restrict__ out) {
    int tok = blockIdx.x;
    int e1  = g_exp[tok * 2 + 0], e2 = g_exp[tok * 2 + 1];
    int p1  = g_pos[tok * 2 + 0], p2 = g_pos[tok * 2 + 1];
    float w1 = g_wt[e1 * MAXPE + p1];
    float w2 = g_wt[e2 * MAXPE + p2];
    size_t s1 = (size_t)(g_offset[e1] + p1) * D_MODEL;
    size_t s2 = (size_t)(g_offset[e2] + p2) * D_MODEL;
    int c = threadIdx.x * 4;
    float4 a1 = *reinterpret_cast<const float4*>(g_O  + s1 + c);
    float4 a2 = *reinterpret_cast<const float4*>(g_O2 + s1 + c);
    float4 c1 = *reinterpret_cast<const float4*>(g_O  + s2 + c);
    float4 c2 = *reinterpret_cast<const float4*>(g_O2 + s2 + c);
    float4 d1 = *reinterpret_cast<const float4*>(b2 + e1 * D_MODEL + c);
    float4 d2 = *reinterpret_cast<const float4*>(b2 + e2 * D_MODEL + c);
    float4 o;
    o.x = w1 * (a1.x + a2.x + d1.x) + w2 * (c1.x + c2.x + d2.x);
    o.y = w1 * (a1.y + a2.y + d1.y) + w2 * (c1.y + c2.y + d2.y);
    o.z = w1 * (a1.z + a2.z + d1.z) + w2 * (c1.z + c2.z + d2.z);
    o.w = w1 * (a1.w + a2.w + d1.w) + w2 * (c1.w + c2.w + d2.w);
    *reinterpret_cast<float4*>(out + (size_t)tok * D_MODEL + c) = o;
}

// ---------------------------------------------------------------------------
extern "C" void kernel_launch(void* const* d_in, const int* in_sizes, int n_in,
                              void* d_out, int out_size) {
    const float* x  = (const float*)d_in[0];
    const float* W1 = (const float*)d_in[1];
    const float* b1 = (const float*)d_in[2];
    const float* W2 = (const float*)d_in[3];
    const float* b2 = (const float*)d_in[4];
    const float* Wg = (const float*)d_in[5];
    float* out = (float*)d_out;

    cudaFuncSetAttribute(ffn_kernel<1>, cudaFuncAttributeMaxDynamicSharedMemorySize, SMEM_BYTES);
    cudaFuncSetAttribute(ffn_kernel<2>, cudaFuncAttributeMaxDynamicSharedMemorySize, SMEM_BYTES);

    reset_kernel<<<1, 32>>>();
    gating_kernel<<<N_TOK / 8, 256>>>(x, Wg);
    offsets_kernel<<<1, 1>>>();
    gatherx_kernel<<<NSLOT, 128>>>(x);
    convW_kernel<1><<<dim3(D_FF / 64, D_MODEL / 64, N_EXP), 256>>>(W1);
    convW_kernel<2><<<dim3(D_MODEL / 64, D_FF / 64, N_EXP), 256>>>(W2);
    ffn_kernel<1><<<dim3(MAXPE / 128, D_FF / 128, N_EXP), 256, SMEM_BYTES>>>(b1);
    // ffn2: y = 16 -> 8 n-tiles x 2 K-halves (split-K)
    ffn_kernel<2><<<dim3(MAXPE / 128, 16, N_EXP), 256, SMEM_BYTES>>>(nullptr);
    combine_kernel<<<N_TOK, 256>>>(b2, out);
}